// round 16
// baseline (speedup 1.0000x reference)
#include <cuda_runtime.h>
#include <cuda_bf16.h>
#include <math_constants.h>
#include <cstdint>

#define B_MAX 4096
#define NF 50
#define E 128
#define A 64
#define M 8
#define FM (NF*M)   // 400
#define NQ 8        // softmax stat splits

#define FPAD 64          // padded friend rows for mma
#define KP 136           // padded k (bf16 elems) -> 272B row stride

// Scratch (no cudaMalloc allowed)
__device__ float g_ak[B_MAX * FM];
__device__ float g_mx[FM];
__device__ float g_se[FM];
__device__ float g_mxq[NQ * FM];
__device__ float g_seq[NQ * FM];

__device__ __forceinline__ unsigned int sptr(const void* p) {
    return (unsigned int)__cvta_generic_to_shared(p);
}

#define LDSM_X4(r0, r1, r2, r3, addr) \
    asm volatile("ldmatrix.sync.aligned.m8n8.x4.shared.b16 {%0,%1,%2,%3}, [%4];" \
                 : "=r"(r0), "=r"(r1), "=r"(r2), "=r"(r3) : "r"(addr))
#define LDSM_X2(r0, r1, addr) \
    asm volatile("ldmatrix.sync.aligned.m8n8.x2.shared.b16 {%0,%1}, [%2];" \
                 : "=r"(r0), "=r"(r1) : "r"(addr))
#define MMA16816(c0, c1, c2, c3, a0, a1, a2, a3, b0, b1) \
    asm volatile("mma.sync.aligned.m16n8k16.row.col.f32.bf16.bf16.f32 " \
                 "{%0,%1,%2,%3}, {%4,%5,%6,%7}, {%8,%9}, {%0,%1,%2,%3};" \
                 : "+f"(c0), "+f"(c1), "+f"(c2), "+f"(c3) \
                 : "r"(a0), "r"(a1), "r"(a2), "r"(a3), "r"(b0), "r"(b1))

// ---------------------------------------------------------------------------
// Kernel 1: att_key on tensor cores (known-good).
// ---------------------------------------------------------------------------
__global__ __launch_bounds__(256, 4) void k_attkey(
    const int* __restrict__ iu, const int* __restrict__ iuf,
    const float* __restrict__ uidW, const float* __restrict__ Key,
    float* __restrict__ akout, int user_pad)
{
    int b = blockIdx.x;
    int tid = threadIdx.x, lane = tid & 31, warp = tid >> 5;

    __shared__ __nv_bfloat16 sFeb[FPAD * KP];
    __shared__ __nv_bfloat16 sKCT[M * KP];
    __shared__ float sC[2][FPAD * M];
    __shared__ float sred[8];

    float uv = 0.f;
    if (tid < E) uv = uidW[(size_t)iu[b] * E + tid];
    float p = uv * uv;
    #pragma unroll
    for (int o = 16; o; o >>= 1) p += __shfl_xor_sync(0xffffffffu, p, o);
    if (lane == 0) sred[warp] = p;
    __syncthreads();
    float n2 = 0.f;
    #pragma unroll
    for (int w = 0; w < 8; w++) n2 += sred[w];
    float inv = 1.f / fmaxf(sqrtf(n2), 1e-12f);

    if (tid < E) {
        float un = uv * inv;
        const float4* K4 = (const float4*)(Key + tid * M);
        float4 k0 = K4[0], k1 = K4[1];
        sKCT[0 * KP + tid] = __float2bfloat16(un * k0.x);
        sKCT[1 * KP + tid] = __float2bfloat16(un * k0.y);
        sKCT[2 * KP + tid] = __float2bfloat16(un * k0.z);
        sKCT[3 * KP + tid] = __float2bfloat16(un * k0.w);
        sKCT[4 * KP + tid] = __float2bfloat16(un * k1.x);
        sKCT[5 * KP + tid] = __float2bfloat16(un * k1.y);
        sKCT[6 * KP + tid] = __float2bfloat16(un * k1.z);
        sKCT[7 * KP + tid] = __float2bfloat16(un * k1.w);
    }

    const int* fids = iuf + b * NF;
    for (int f = warp; f < NF; f += 8) {
        int fid = fids[f];
        float fnm = (fid != user_pad) ? 1.f : 0.f;
        float4 v = *(const float4*)(uidW + (size_t)fid * E + lane * 4);
        v.x *= fnm; v.y *= fnm; v.z *= fnm; v.w *= fnm;
        float s = v.x * v.x + v.y * v.y + v.z * v.z + v.w * v.w;
        #pragma unroll
        for (int o = 16; o; o >>= 1) s += __shfl_xor_sync(0xffffffffu, s, o);
        float invf = 1.f / fmaxf(sqrtf(s), 1e-12f);
        __nv_bfloat162 p0 = __floats2bfloat162_rn(v.x * invf, v.y * invf);
        __nv_bfloat162 p1 = __floats2bfloat162_rn(v.z * invf, v.w * invf);
        unsigned long long packed =
            ((unsigned long long)(*(unsigned int*)&p1) << 32) | (*(unsigned int*)&p0);
        *(unsigned long long*)&sFeb[f * KP + lane * 4] = packed;
    }
    __syncthreads();

    {
        int mt = warp & 3, kh = warp >> 2;
        float c0 = 0.f, c1 = 0.f, c2 = 0.f, c3 = 0.f;
        unsigned int aBase = sptr(sFeb) + (mt * 16 + (lane & 15)) * (KP * 2)
                           + ((lane >> 4) << 4) + kh * 128;
        unsigned int bBase = sptr(sKCT) + (lane & 7) * (KP * 2)
                           + (((lane >> 3) & 1) << 4) + kh * 128;
        #pragma unroll
        for (int ks = 0; ks < 4; ks++) {
            unsigned int a0, a1, a2, a3, b0, b1;
            LDSM_X4(a0, a1, a2, a3, aBase + ks * 32);
            LDSM_X2(b0, b1, bBase + ks * 32);
            MMA16816(c0, c1, c2, c3, a0, a1, a2, a3, b0, b1);
        }
        int row = mt * 16 + (lane >> 2);
        int col = (lane & 3) * 2;
        sC[kh][row * M + col]           = c0;
        sC[kh][row * M + col + 1]       = c1;
        sC[kh][(row + 8) * M + col]     = c2;
        sC[kh][(row + 8) * M + col + 1] = c3;
    }
    __syncthreads();

    float* akb = akout + (size_t)b * FM;
    for (int idx = tid; idx < FM; idx += 256)
        akb[idx] = sC[0][idx] + sC[1][idx];
}

// ---------------------------------------------------------------------------
// Kernel 2a: partial softmax stats per (friend, batch-eighth).
// ---------------------------------------------------------------------------
__global__ __launch_bounds__(256) void k_softstats_part(
    const float* __restrict__ ak, float* __restrict__ mxq,
    float* __restrict__ seq, int nb)
{
    int f = blockIdx.x, q = blockIdx.y;
    int b0 = (nb * q) / NQ, b1 = (nb * (q + 1)) / NQ;
    int tid = threadIdx.x, lane = tid & 31, warp = tid >> 5;
    __shared__ float sredm[8][8];
    __shared__ float sreds[8][8];

    float mv[8];
    #pragma unroll
    for (int m = 0; m < 8; m++) mv[m] = -CUDART_INF_F;
    for (int b = b0 + tid; b < b1; b += 256) {
        const float4* p = (const float4*)(ak + (size_t)b * FM + f * 8);
        float4 x0 = p[0], x1 = p[1];
        mv[0] = fmaxf(mv[0], x0.x); mv[1] = fmaxf(mv[1], x0.y);
        mv[2] = fmaxf(mv[2], x0.z); mv[3] = fmaxf(mv[3], x0.w);
        mv[4] = fmaxf(mv[4], x1.x); mv[5] = fmaxf(mv[5], x1.y);
        mv[6] = fmaxf(mv[6], x1.z); mv[7] = fmaxf(mv[7], x1.w);
    }
    #pragma unroll
    for (int m = 0; m < 8; m++) {
        #pragma unroll
        for (int o = 16; o; o >>= 1) mv[m] = fmaxf(mv[m], __shfl_xor_sync(0xffffffffu, mv[m], o));
    }
    if (lane == 0) {
        #pragma unroll
        for (int m = 0; m < 8; m++) sredm[warp][m] = mv[m];
    }
    __syncthreads();
    float mm[8];
    #pragma unroll
    for (int m = 0; m < 8; m++) {
        float v = sredm[0][m];
        #pragma unroll
        for (int w = 1; w < 8; w++) v = fmaxf(v, sredm[w][m]);
        mm[m] = v;
    }

    float sv[8] = {0,0,0,0,0,0,0,0};
    for (int b = b0 + tid; b < b1; b += 256) {
        const float4* p = (const float4*)(ak + (size_t)b * FM + f * 8);
        float4 x0 = p[0], x1 = p[1];
        sv[0] += __expf(x0.x - mm[0]); sv[1] += __expf(x0.y - mm[1]);
        sv[2] += __expf(x0.z - mm[2]); sv[3] += __expf(x0.w - mm[3]);
        sv[4] += __expf(x1.x - mm[4]); sv[5] += __expf(x1.y - mm[5]);
        sv[6] += __expf(x1.z - mm[6]); sv[7] += __expf(x1.w - mm[7]);
    }
    #pragma unroll
    for (int m = 0; m < 8; m++) {
        #pragma unroll
        for (int o = 16; o; o >>= 1) sv[m] += __shfl_xor_sync(0xffffffffu, sv[m], o);
    }
    if (lane == 0) {
        #pragma unroll
        for (int m = 0; m < 8; m++) sreds[warp][m] = sv[m];
    }
    __syncthreads();
    if (tid < 8) {
        float s = 0.f;
        #pragma unroll
        for (int w = 0; w < 8; w++) s += sreds[w][tid];
        mxq[q * FM + f * 8 + tid] = mm[tid];
        seq[q * FM + f * 8 + tid] = s;
    }
}

__global__ __launch_bounds__(512) void k_softstats_comb(
    const float* __restrict__ mxq, const float* __restrict__ seq,
    float* __restrict__ mx, float* __restrict__ se)
{
    int i = threadIdx.x;
    if (i >= FM) return;
    float mg = -CUDART_INF_F;
    #pragma unroll
    for (int q = 0; q < NQ; q++) mg = fmaxf(mg, mxq[q * FM + i]);
    float s = 0.f;
    #pragma unroll
    for (int q = 0; q < NQ; q++) s += seq[q * FM + i] * __expf(mxq[q * FM + i] - mg);
    mx[i] = mg;
    se[i] = s;
}

// ---------------------------------------------------------------------------
// Kernel 3: FOUR batches per block, pipelined sAm, and fused Phase-D/score:
// score = uid·iid + (Σ_f jw_f (f2_f·iid)) / jsum + bias  -> 4 barriers/batch.
// ---------------------------------------------------------------------------
__global__ __launch_bounds__(256, 4) void k_main(
    const int* __restrict__ iu, const int* __restrict__ ii,
    const int* __restrict__ iuf, const float* __restrict__ uidW,
    const float* __restrict__ iidW, const float* __restrict__ ibias,
    const float* __restrict__ Memw, const float* __restrict__ WA,
    const float* __restrict__ BA, const float* __restrict__ Uo,
    const float* __restrict__ ak, const float* __restrict__ mx,
    const float* __restrict__ se, float* __restrict__ out,
    int user_pad, int nbTotal)
{
    int tid = threadIdx.x, lane = tid & 31, warp = tid >> 5;
    int ep = tid & 63, grp = tid >> 6;

    extern __shared__ char smraw[];
    __nv_bfloat16* sF2b = (__nv_bfloat16*)smraw;                 // 17408
    __nv_bfloat16* sWAT = (__nv_bfloat16*)(smraw + 17408);       // 17408 -> 34816
    float*  sAm   = (float*)(smraw + 34816);                     // 2 x 1600 -> 38016
    float*  sJ    = (float*)(smraw + 38016);                     // 256 -> 38272
    float*  sJP   = (float*)(smraw + 38272);                     // 512 -> 38784
    float2* sBU   = (float2*)(smraw + 38784);                    // 512 -> 39296
    float*  sredJ = (float*)(smraw + 39296);                     // 32
    float*  sredF = (float*)(smraw + 39328);                     // 32
    float*  sredU = (float*)(smraw + 39360);                     // 32 -> 39392

    // --- batch-invariant staging + first sAm fill (one barrier) ---
    if (tid < A) sBU[tid] = make_float2(BA[tid], Uo[tid]);
    #pragma unroll
    for (int it = 0; it < 16; it++) {
        int idx = tid + it * 256;
        int n = idx & 63, k = (idx >> 6) * 2;
        __nv_bfloat162 w2 = __floats2bfloat162_rn(WA[k * A + n], WA[(k + 1) * A + n]);
        *(__nv_bfloat162*)&sWAT[n * KP + k] = w2;
    }
    float2 mr[8];
    #pragma unroll
    for (int m = 0; m < 8; m++) mr[m] = *(const float2*)(Memw + m * E + ep * 2);

    int b0 = blockIdx.x * 4;
    {
        const int* fids = iuf + b0 * NF;
        const float* akb = ak + (size_t)b0 * FM;
        for (int i = tid; i < FM; i += 256) {
            int f = i >> 3;
            float fnm = (fids[f] != user_pad) ? 1.f : 0.f;
            sAm[i] = fnm * __expf(akb[i] - mx[i]) / se[i];
        }
    }
    __syncthreads();

    for (int bi = 0; bi < 4; bi++) {
        int b = b0 + bi;
        if (b >= nbTotal) break;
        const int* fids = iuf + b * NF;
        const float* sAmc = sAm + (bi & 1) * FM;

        // --- Phase A: f2 ; tail: prefetch next batch's sAm into other buffer ---
        for (int f = grp; f < NF; f += 4) {
            float2 fe2 = *(const float2*)(uidW + (size_t)fids[f] * E + ep * 2);
            const float4* am4 = (const float4*)(sAmc + f * 8);
            float4 a0 = am4[0], a1 = am4[1];
            float f1x, f1y;
            f1x = a0.x * mr[0].x; f1y = a0.x * mr[0].y;
            f1x = fmaf(a0.y, mr[1].x, f1x); f1y = fmaf(a0.y, mr[1].y, f1y);
            f1x = fmaf(a0.z, mr[2].x, f1x); f1y = fmaf(a0.z, mr[2].y, f1y);
            f1x = fmaf(a0.w, mr[3].x, f1x); f1y = fmaf(a0.w, mr[3].y, f1y);
            f1x = fmaf(a1.x, mr[4].x, f1x); f1y = fmaf(a1.x, mr[4].y, f1y);
            f1x = fmaf(a1.y, mr[5].x, f1x); f1y = fmaf(a1.y, mr[5].y, f1y);
            f1x = fmaf(a1.z, mr[6].x, f1x); f1y = fmaf(a1.z, mr[6].y, f1y);
            f1x = fmaf(a1.w, mr[7].x, f1x); f1y = fmaf(a1.w, mr[7].y, f1y);
            *(__nv_bfloat162*)&sF2b[f * KP + ep * 2] =
                __floats2bfloat162_rn(f1x * fe2.x, f1y * fe2.y);
        }
        if (bi < 3 && b + 1 < nbTotal) {
            const int* fidsN = iuf + (b + 1) * NF;
            const float* akbN = ak + (size_t)(b + 1) * FM;
            float* sAmN = sAm + ((bi + 1) & 1) * FM;
            for (int i = tid; i < FM; i += 256) {
                int f = i >> 3;
                float fnm = (fidsN[f] != user_pad) ? 1.f : 0.f;
                sAmN[i] = fnm * __expf(akbN[i] - mx[i]) / se[i];
            }
        }
        __syncthreads();

        // --- Phase B: MMA + in-register epilogue -> sJP[kh][row] ---
        {
            int mt = warp & 3;
            int kh = warp >> 2;
            int ntb = kh * 4;
            float c0[4], c1[4], c2[4], c3[4];
            #pragma unroll
            for (int t = 0; t < 4; t++) { c0[t] = c1[t] = c2[t] = c3[t] = 0.f; }

            unsigned int aBase = sptr(sF2b) + (mt * 16 + (lane & 15)) * (KP * 2) + ((lane >> 4) << 4);
            unsigned int bBase = sptr(sWAT) + (lane & 7) * (KP * 2) + (((lane >> 3) & 1) << 4);

            #pragma unroll
            for (int ks = 0; ks < 8; ks++) {
                unsigned int a0, a1, a2, a3;
                LDSM_X4(a0, a1, a2, a3, aBase + ks * 32);
                #pragma unroll
                for (int t = 0; t < 4; t++) {
                    unsigned int b0r, b1r;
                    LDSM_X2(b0r, b1r, bBase + (ntb + t) * 8 * (KP * 2) + ks * 32);
                    MMA16816(c0[t], c1[t], c2[t], c3[t], a0, a1, a2, a3, b0r, b1r);
                }
            }

            float jp0 = 0.f, jp1 = 0.f;
            #pragma unroll
            for (int t = 0; t < 4; t++) {
                int col = ntb * 8 + t * 8 + (lane & 3) * 2;
                float2 bu0 = sBU[col], bu1 = sBU[col + 1];
                jp0 += fmaxf(c0[t] + bu0.x, 0.f) * bu0.y + fmaxf(c1[t] + bu1.x, 0.f) * bu1.y;
                jp1 += fmaxf(c2[t] + bu0.x, 0.f) * bu0.y + fmaxf(c3[t] + bu1.x, 0.f) * bu1.y;
            }
            jp0 += __shfl_xor_sync(0xffffffffu, jp0, 1);
            jp0 += __shfl_xor_sync(0xffffffffu, jp0, 2);
            jp1 += __shfl_xor_sync(0xffffffffu, jp1, 1);
            jp1 += __shfl_xor_sync(0xffffffffu, jp1, 2);
            if ((lane & 3) == 0) {
                int row = mt * 16 + (lane >> 2);
                sJP[kh * 64 + row]     = jp0;
                sJP[kh * 64 + row + 8] = jp1;
            }
        }
        __syncthreads();

        // --- j[f] + jsum (64 threads) ---
        if (tid < 64) {
            float j = 0.f;
            if (tid < NF) {
                float fnm = (fids[tid] != user_pad) ? 1.f : 0.f;
                j = fnm * __expf(sJP[tid] + sJP[64 + tid]);
                sJ[tid] = j;
            }
            float jj = j;
            #pragma unroll
            for (int o = 16; o; o >>= 1) jj += __shfl_xor_sync(0xffffffffu, jj, o);
            if (lane == 0) sredJ[warp] = jj;
        }
        __syncthreads();

        // --- Fused Phase D + score partials (iid folded in registers) ---
        {
            int it = ii[b];
            float2 iid2 = *(const float2*)(iidW + (size_t)it * E + ep * 2);
            float pp = 0.f;
            for (int f = grp; f < NF; f += 4) {
                float jw = sJ[f];
                float2 f2v = __bfloat1622float2(*(const __nv_bfloat162*)&sF2b[f * KP + ep * 2]);
                pp = fmaf(jw, f2v.x * iid2.x + f2v.y * iid2.y, pp);
            }
            float qq = 0.f;
            if (grp == 0) {
                float2 uid2 = *(const float2*)(uidW + (size_t)iu[b] * E + ep * 2);
                qq = uid2.x * iid2.x + uid2.y * iid2.y;
            }
            #pragma unroll
            for (int o = 16; o; o >>= 1) {
                pp += __shfl_xor_sync(0xffffffffu, pp, o);
                qq += __shfl_xor_sync(0xffffffffu, qq, o);
            }
            if (lane == 0) { sredF[warp] = pp; sredU[warp] = qq; }
        }
        __syncthreads();

        if (tid == 0) {
            float jsum = sredJ[0] + sredJ[1];
            float fr = 0.f, ud = 0.f;
            #pragma unroll
            for (int w = 0; w < 8; w++) { fr += sredF[w]; ud += sredU[w]; }
            out[b] = ud + fr / (jsum + 1e-8f) + ibias[ii[b]];
        }
    }
}

// ---------------------------------------------------------------------------
extern "C" void kernel_launch(void* const* d_in, const int* in_sizes, int n_in,
                              void* d_out, int out_size)
{
    const int*   input_u  = (const int*)d_in[0];
    const int*   input_i  = (const int*)d_in[1];
    const int*   input_uf = (const int*)d_in[2];
    const float* uidW     = (const float*)d_in[3];
    const float* iidW     = (const float*)d_in[4];
    const float* i_bias   = (const float*)d_in[5];
    const float* Key      = (const float*)d_in[6];
    const float* Memw     = (const float*)d_in[7];
    const float* WA       = (const float*)d_in[8];
    const float* BA       = (const float*)d_in[9];
    const float* Uo       = (const float*)d_in[10];
    float* out = (float*)d_out;

    int nb = in_sizes[0];
    int user_pad = in_sizes[3] / E - 1;

    float *g_ak_p, *g_mx_p, *g_se_p, *g_mxq_p, *g_seq_p;
    cudaGetSymbolAddress((void**)&g_ak_p, g_ak);
    cudaGetSymbolAddress((void**)&g_mx_p, g_mx);
    cudaGetSymbolAddress((void**)&g_se_p, g_se);
    cudaGetSymbolAddress((void**)&g_mxq_p, g_mxq);
    cudaGetSymbolAddress((void**)&g_seq_p, g_seq);

    const int kmain_smem = 39392;
    static int attr_set = 0;
    if (!attr_set) {
        cudaFuncSetAttribute(k_main, cudaFuncAttributeMaxDynamicSharedMemorySize, kmain_smem);
        attr_set = 1;
    }

    k_attkey<<<nb, 256>>>(input_u, input_uf, uidW, Key, g_ak_p, user_pad);
    k_softstats_part<<<dim3(NF, NQ), 256>>>(g_ak_p, g_mxq_p, g_seq_p, nb);
    k_softstats_comb<<<1, 512>>>(g_mxq_p, g_seq_p, g_mx_p, g_se_p);
    k_main<<<(nb + 3) / 4, 256, kmain_smem>>>(input_u, input_i, input_uf, uidW, iidW, i_bias,
                                              Memw, WA, BA, Uo, g_ak_p, g_mx_p, g_se_p, out,
                                              user_pad, nb);
}

// round 17
// speedup vs baseline: 1.0566x; 1.0566x over previous
#include <cuda_runtime.h>
#include <cuda_bf16.h>
#include <math_constants.h>
#include <cstdint>

#define B_MAX 4096
#define NF 50
#define E 128
#define A 64
#define M 8
#define FM (NF*M)   // 400
#define NQ 8        // softmax stat splits

#define FPAD 64          // padded friend rows for mma
#define KP 136           // padded k (bf16 elems) -> 272B row stride

// Scratch (no cudaMalloc allowed)
__device__ float g_ak[B_MAX * FM];
__device__ float g_seq[NQ * FM];

__device__ __forceinline__ unsigned int sptr(const void* p) {
    return (unsigned int)__cvta_generic_to_shared(p);
}

#define LDSM_X4(r0, r1, r2, r3, addr) \
    asm volatile("ldmatrix.sync.aligned.m8n8.x4.shared.b16 {%0,%1,%2,%3}, [%4];" \
                 : "=r"(r0), "=r"(r1), "=r"(r2), "=r"(r3) : "r"(addr))
#define LDSM_X2(r0, r1, addr) \
    asm volatile("ldmatrix.sync.aligned.m8n8.x2.shared.b16 {%0,%1}, [%2];" \
                 : "=r"(r0), "=r"(r1) : "r"(addr))
#define MMA16816(c0, c1, c2, c3, a0, a1, a2, a3, b0, b1) \
    asm volatile("mma.sync.aligned.m16n8k16.row.col.f32.bf16.bf16.f32 " \
                 "{%0,%1,%2,%3}, {%4,%5,%6,%7}, {%8,%9}, {%0,%1,%2,%3};" \
                 : "+f"(c0), "+f"(c1), "+f"(c2), "+f"(c3) \
                 : "r"(a0), "r"(a1), "r"(a2), "r"(a3), "r"(b0), "r"(b1))

// ---------------------------------------------------------------------------
// Kernel 1: att_key on tensor cores (known-good, unchanged).
// ---------------------------------------------------------------------------
__global__ __launch_bounds__(256, 4) void k_attkey(
    const int* __restrict__ iu, const int* __restrict__ iuf,
    const float* __restrict__ uidW, const float* __restrict__ Key,
    float* __restrict__ akout, int user_pad)
{
    int b = blockIdx.x;
    int tid = threadIdx.x, lane = tid & 31, warp = tid >> 5;

    __shared__ __nv_bfloat16 sFeb[FPAD * KP];
    __shared__ __nv_bfloat16 sKCT[M * KP];
    __shared__ float sC[2][FPAD * M];
    __shared__ float sred[8];

    float uv = 0.f;
    if (tid < E) uv = uidW[(size_t)iu[b] * E + tid];
    float p = uv * uv;
    #pragma unroll
    for (int o = 16; o; o >>= 1) p += __shfl_xor_sync(0xffffffffu, p, o);
    if (lane == 0) sred[warp] = p;
    __syncthreads();
    float n2 = 0.f;
    #pragma unroll
    for (int w = 0; w < 8; w++) n2 += sred[w];
    float inv = 1.f / fmaxf(sqrtf(n2), 1e-12f);

    if (tid < E) {
        float un = uv * inv;
        const float4* K4 = (const float4*)(Key + tid * M);
        float4 k0 = K4[0], k1 = K4[1];
        sKCT[0 * KP + tid] = __float2bfloat16(un * k0.x);
        sKCT[1 * KP + tid] = __float2bfloat16(un * k0.y);
        sKCT[2 * KP + tid] = __float2bfloat16(un * k0.z);
        sKCT[3 * KP + tid] = __float2bfloat16(un * k0.w);
        sKCT[4 * KP + tid] = __float2bfloat16(un * k1.x);
        sKCT[5 * KP + tid] = __float2bfloat16(un * k1.y);
        sKCT[6 * KP + tid] = __float2bfloat16(un * k1.z);
        sKCT[7 * KP + tid] = __float2bfloat16(un * k1.w);
    }

    const int* fids = iuf + b * NF;
    for (int f = warp; f < NF; f += 8) {
        int fid = fids[f];
        float fnm = (fid != user_pad) ? 1.f : 0.f;
        float4 v = *(const float4*)(uidW + (size_t)fid * E + lane * 4);
        v.x *= fnm; v.y *= fnm; v.z *= fnm; v.w *= fnm;
        float s = v.x * v.x + v.y * v.y + v.z * v.z + v.w * v.w;
        #pragma unroll
        for (int o = 16; o; o >>= 1) s += __shfl_xor_sync(0xffffffffu, s, o);
        float invf = 1.f / fmaxf(sqrtf(s), 1e-12f);
        __nv_bfloat162 p0 = __floats2bfloat162_rn(v.x * invf, v.y * invf);
        __nv_bfloat162 p1 = __floats2bfloat162_rn(v.z * invf, v.w * invf);
        unsigned long long packed =
            ((unsigned long long)(*(unsigned int*)&p1) << 32) | (*(unsigned int*)&p0);
        *(unsigned long long*)&sFeb[f * KP + lane * 4] = packed;
    }
    __syncthreads();

    {
        int mt = warp & 3, kh = warp >> 2;
        float c0 = 0.f, c1 = 0.f, c2 = 0.f, c3 = 0.f;
        unsigned int aBase = sptr(sFeb) + (mt * 16 + (lane & 15)) * (KP * 2)
                           + ((lane >> 4) << 4) + kh * 128;
        unsigned int bBase = sptr(sKCT) + (lane & 7) * (KP * 2)
                           + (((lane >> 3) & 1) << 4) + kh * 128;
        #pragma unroll
        for (int ks = 0; ks < 4; ks++) {
            unsigned int a0, a1, a2, a3, b0, b1;
            LDSM_X4(a0, a1, a2, a3, aBase + ks * 32);
            LDSM_X2(b0, b1, bBase + ks * 32);
            MMA16816(c0, c1, c2, c3, a0, a1, a2, a3, b0, b1);
        }
        int row = mt * 16 + (lane >> 2);
        int col = (lane & 3) * 2;
        sC[kh][row * M + col]           = c0;
        sC[kh][row * M + col + 1]       = c1;
        sC[kh][(row + 8) * M + col]     = c2;
        sC[kh][(row + 8) * M + col + 1] = c3;
    }
    __syncthreads();

    float* akb = akout + (size_t)b * FM;
    for (int idx = tid; idx < FM; idx += 256)
        akb[idx] = sC[0][idx] + sC[1][idx];
}

// ---------------------------------------------------------------------------
// Kernel 2: partial sum-exp per (friend, batch-eighth). Single pass — ak is
// bounded (|ak| <~ 0.66 by construction), so no max subtraction is needed:
// exp(ak)/sum(exp(ak)) == softmax(ak) exactly.
// ---------------------------------------------------------------------------
__global__ __launch_bounds__(256) void k_softstats_part(
    const float* __restrict__ ak, float* __restrict__ seq, int nb)
{
    int f = blockIdx.x, q = blockIdx.y;
    int b0 = (nb * q) / NQ, b1 = (nb * (q + 1)) / NQ;
    int tid = threadIdx.x, lane = tid & 31, warp = tid >> 5;
    __shared__ float sreds[8][8];

    float sv[8] = {0,0,0,0,0,0,0,0};
    for (int b = b0 + tid; b < b1; b += 256) {
        const float4* p = (const float4*)(ak + (size_t)b * FM + f * 8);
        float4 x0 = p[0], x1 = p[1];
        sv[0] += __expf(x0.x); sv[1] += __expf(x0.y);
        sv[2] += __expf(x0.z); sv[3] += __expf(x0.w);
        sv[4] += __expf(x1.x); sv[5] += __expf(x1.y);
        sv[6] += __expf(x1.z); sv[7] += __expf(x1.w);
    }
    #pragma unroll
    for (int m = 0; m < 8; m++) {
        #pragma unroll
        for (int o = 16; o; o >>= 1) sv[m] += __shfl_xor_sync(0xffffffffu, sv[m], o);
    }
    if (lane == 0) {
        #pragma unroll
        for (int m = 0; m < 8; m++) sreds[warp][m] = sv[m];
    }
    __syncthreads();
    if (tid < 8) {
        float s = 0.f;
        #pragma unroll
        for (int w = 0; w < 8; w++) s += sreds[w][tid];
        seq[q * FM + f * 8 + tid] = s;
    }
}

// ---------------------------------------------------------------------------
// Kernel 3: FOUR batches per block, pipelined sAm, fused Phase-D/score.
// Folds the 8-partial sum-exp combine (plain adds) into block start and
// stores reciprocals so the sAm fill is a multiply.
// ---------------------------------------------------------------------------
__global__ __launch_bounds__(256, 4) void k_main(
    const int* __restrict__ iu, const int* __restrict__ ii,
    const int* __restrict__ iuf, const float* __restrict__ uidW,
    const float* __restrict__ iidW, const float* __restrict__ ibias,
    const float* __restrict__ Memw, const float* __restrict__ WA,
    const float* __restrict__ BA, const float* __restrict__ Uo,
    const float* __restrict__ ak, const float* __restrict__ seq,
    float* __restrict__ out, int user_pad, int nbTotal)
{
    int tid = threadIdx.x, lane = tid & 31, warp = tid >> 5;
    int ep = tid & 63, grp = tid >> 6;

    extern __shared__ char smraw[];
    __nv_bfloat16* sF2b = (__nv_bfloat16*)smraw;                 // 17408
    __nv_bfloat16* sWAT = (__nv_bfloat16*)(smraw + 17408);       // 17408 -> 34816
    float*  sAm   = (float*)(smraw + 34816);                     // 2 x 1600 -> 38016
    float*  sRSE  = (float*)(smraw + 38016);                     // 1600 -> 39616
    float*  sJ    = (float*)(smraw + 39616);                     // 256 -> 39872
    float*  sJP   = (float*)(smraw + 39872);                     // 512 -> 40384
    float2* sBU   = (float2*)(smraw + 40384);                    // 512 -> 40896
    float*  sredJ = (float*)(smraw + 40896);                     // 32
    float*  sredF = (float*)(smraw + 40928);                     // 32
    float*  sredU = (float*)(smraw + 40960);                     // 32 -> 40992

    // --- batch-invariant staging + reciprocal sum-exp combine ---
    if (tid < A) sBU[tid] = make_float2(BA[tid], Uo[tid]);
    #pragma unroll
    for (int it = 0; it < 16; it++) {
        int idx = tid + it * 256;
        int n = idx & 63, k = (idx >> 6) * 2;
        __nv_bfloat162 w2 = __floats2bfloat162_rn(WA[k * A + n], WA[(k + 1) * A + n]);
        *(__nv_bfloat162*)&sWAT[n * KP + k] = w2;
    }
    for (int i = tid; i < FM; i += 256) {
        float s = 0.f;
        #pragma unroll
        for (int q = 0; q < NQ; q++) s += seq[q * FM + i];
        sRSE[i] = 1.f / s;
    }
    float2 mr[8];
    #pragma unroll
    for (int m = 0; m < 8; m++) mr[m] = *(const float2*)(Memw + m * E + ep * 2);
    __syncthreads();

    int b0 = blockIdx.x * 4;
    {
        const int* fids = iuf + b0 * NF;
        const float* akb = ak + (size_t)b0 * FM;
        for (int i = tid; i < FM; i += 256) {
            int f = i >> 3;
            float fnm = (fids[f] != user_pad) ? 1.f : 0.f;
            sAm[i] = fnm * __expf(akb[i]) * sRSE[i];
        }
    }
    __syncthreads();

    for (int bi = 0; bi < 4; bi++) {
        int b = b0 + bi;
        if (b >= nbTotal) break;
        const int* fids = iuf + b * NF;
        const float* sAmc = sAm + (bi & 1) * FM;

        // --- Phase A: f2 ; tail: prefetch next batch's sAm ---
        for (int f = grp; f < NF; f += 4) {
            float2 fe2 = *(const float2*)(uidW + (size_t)fids[f] * E + ep * 2);
            const float4* am4 = (const float4*)(sAmc + f * 8);
            float4 a0 = am4[0], a1 = am4[1];
            float f1x, f1y;
            f1x = a0.x * mr[0].x; f1y = a0.x * mr[0].y;
            f1x = fmaf(a0.y, mr[1].x, f1x); f1y = fmaf(a0.y, mr[1].y, f1y);
            f1x = fmaf(a0.z, mr[2].x, f1x); f1y = fmaf(a0.z, mr[2].y, f1y);
            f1x = fmaf(a0.w, mr[3].x, f1x); f1y = fmaf(a0.w, mr[3].y, f1y);
            f1x = fmaf(a1.x, mr[4].x, f1x); f1y = fmaf(a1.x, mr[4].y, f1y);
            f1x = fmaf(a1.y, mr[5].x, f1x); f1y = fmaf(a1.y, mr[5].y, f1y);
            f1x = fmaf(a1.z, mr[6].x, f1x); f1y = fmaf(a1.z, mr[6].y, f1y);
            f1x = fmaf(a1.w, mr[7].x, f1x); f1y = fmaf(a1.w, mr[7].y, f1y);
            *(__nv_bfloat162*)&sF2b[f * KP + ep * 2] =
                __floats2bfloat162_rn(f1x * fe2.x, f1y * fe2.y);
        }
        if (bi < 3 && b + 1 < nbTotal) {
            const int* fidsN = iuf + (b + 1) * NF;
            const float* akbN = ak + (size_t)(b + 1) * FM;
            float* sAmN = sAm + ((bi + 1) & 1) * FM;
            for (int i = tid; i < FM; i += 256) {
                int f = i >> 3;
                float fnm = (fidsN[f] != user_pad) ? 1.f : 0.f;
                sAmN[i] = fnm * __expf(akbN[i]) * sRSE[i];
            }
        }
        __syncthreads();

        // --- Phase B: MMA + in-register epilogue -> sJP[kh][row] ---
        {
            int mt = warp & 3;
            int kh = warp >> 2;
            int ntb = kh * 4;
            float c0[4], c1[4], c2[4], c3[4];
            #pragma unroll
            for (int t = 0; t < 4; t++) { c0[t] = c1[t] = c2[t] = c3[t] = 0.f; }

            unsigned int aBase = sptr(sF2b) + (mt * 16 + (lane & 15)) * (KP * 2) + ((lane >> 4) << 4);
            unsigned int bBase = sptr(sWAT) + (lane & 7) * (KP * 2) + (((lane >> 3) & 1) << 4);

            #pragma unroll
            for (int ks = 0; ks < 8; ks++) {
                unsigned int a0, a1, a2, a3;
                LDSM_X4(a0, a1, a2, a3, aBase + ks * 32);
                #pragma unroll
                for (int t = 0; t < 4; t++) {
                    unsigned int b0r, b1r;
                    LDSM_X2(b0r, b1r, bBase + (ntb + t) * 8 * (KP * 2) + ks * 32);
                    MMA16816(c0[t], c1[t], c2[t], c3[t], a0, a1, a2, a3, b0r, b1r);
                }
            }

            float jp0 = 0.f, jp1 = 0.f;
            #pragma unroll
            for (int t = 0; t < 4; t++) {
                int col = ntb * 8 + t * 8 + (lane & 3) * 2;
                float2 bu0 = sBU[col], bu1 = sBU[col + 1];
                jp0 += fmaxf(c0[t] + bu0.x, 0.f) * bu0.y + fmaxf(c1[t] + bu1.x, 0.f) * bu1.y;
                jp1 += fmaxf(c2[t] + bu0.x, 0.f) * bu0.y + fmaxf(c3[t] + bu1.x, 0.f) * bu1.y;
            }
            jp0 += __shfl_xor_sync(0xffffffffu, jp0, 1);
            jp0 += __shfl_xor_sync(0xffffffffu, jp0, 2);
            jp1 += __shfl_xor_sync(0xffffffffu, jp1, 1);
            jp1 += __shfl_xor_sync(0xffffffffu, jp1, 2);
            if ((lane & 3) == 0) {
                int row = mt * 16 + (lane >> 2);
                sJP[kh * 64 + row]     = jp0;
                sJP[kh * 64 + row + 8] = jp1;
            }
        }
        __syncthreads();

        // --- j[f] + jsum (64 threads) ---
        if (tid < 64) {
            float j = 0.f;
            if (tid < NF) {
                float fnm = (fids[tid] != user_pad) ? 1.f : 0.f;
                j = fnm * __expf(sJP[tid] + sJP[64 + tid]);
                sJ[tid] = j;
            }
            float jj = j;
            #pragma unroll
            for (int o = 16; o; o >>= 1) jj += __shfl_xor_sync(0xffffffffu, jj, o);
            if (lane == 0) sredJ[warp] = jj;
        }
        __syncthreads();

        // --- Fused Phase D + score partials (iid folded in registers) ---
        {
            int it = ii[b];
            float2 iid2 = *(const float2*)(iidW + (size_t)it * E + ep * 2);
            float pp = 0.f;
            for (int f = grp; f < NF; f += 4) {
                float jw = sJ[f];
                float2 f2v = __bfloat1622float2(*(const __nv_bfloat162*)&sF2b[f * KP + ep * 2]);
                pp = fmaf(jw, f2v.x * iid2.x + f2v.y * iid2.y, pp);
            }
            float qq = 0.f;
            if (grp == 0) {
                float2 uid2 = *(const float2*)(uidW + (size_t)iu[b] * E + ep * 2);
                qq = uid2.x * iid2.x + uid2.y * iid2.y;
            }
            #pragma unroll
            for (int o = 16; o; o >>= 1) {
                pp += __shfl_xor_sync(0xffffffffu, pp, o);
                qq += __shfl_xor_sync(0xffffffffu, qq, o);
            }
            if (lane == 0) { sredF[warp] = pp; sredU[warp] = qq; }
        }
        __syncthreads();

        if (tid == 0) {
            float jsum = sredJ[0] + sredJ[1];
            float fr = 0.f, ud = 0.f;
            #pragma unroll
            for (int w = 0; w < 8; w++) { fr += sredF[w]; ud += sredU[w]; }
            out[b] = ud + fr / (jsum + 1e-8f) + ibias[ii[b]];
        }
    }
}

// ---------------------------------------------------------------------------
extern "C" void kernel_launch(void* const* d_in, const int* in_sizes, int n_in,
                              void* d_out, int out_size)
{
    const int*   input_u  = (const int*)d_in[0];
    const int*   input_i  = (const int*)d_in[1];
    const int*   input_uf = (const int*)d_in[2];
    const float* uidW     = (const float*)d_in[3];
    const float* iidW     = (const float*)d_in[4];
    const float* i_bias   = (const float*)d_in[5];
    const float* Key      = (const float*)d_in[6];
    const float* Memw     = (const float*)d_in[7];
    const float* WA       = (const float*)d_in[8];
    const float* BA       = (const float*)d_in[9];
    const float* Uo       = (const float*)d_in[10];
    float* out = (float*)d_out;

    int nb = in_sizes[0];
    int user_pad = in_sizes[3] / E - 1;

    float *g_ak_p, *g_seq_p;
    cudaGetSymbolAddress((void**)&g_ak_p, g_ak);
    cudaGetSymbolAddress((void**)&g_seq_p, g_seq);

    const int kmain_smem = 40992;
    static int attr_set = 0;
    if (!attr_set) {
        cudaFuncSetAttribute(k_main, cudaFuncAttributeMaxDynamicSharedMemorySize, kmain_smem);
        attr_set = 1;
    }

    k_attkey<<<nb, 256>>>(input_u, input_uf, uidW, Key, g_ak_p, user_pad);
    k_softstats_part<<<dim3(NF, NQ), 256>>>(g_ak_p, g_seq_p, nb);
    k_main<<<(nb + 3) / 4, 256, kmain_smem>>>(input_u, input_i, input_uf, uidW, iidW, i_bias,
                                              Memw, WA, BA, Uo, g_ak_p, g_seq_p, out,
                                              user_pad, nb);
}